// round 6
// baseline (speedup 1.0000x reference)
#include <cuda_runtime.h>
#include <cstdint>

#define Bsz 4096
#define Hd  512
#define G4  2048
#define Av  64
#define Tlen 16
#define PADTOK 64
#define BOSTOK 65

// ---------------- scratch (static device globals; no allocation) ----------------
__device__ __align__(16) float g_h[Bsz * Hd];
__device__ __align__(16) float g_c[Bsz * Hd];
__device__ __align__(16) float g_gates[Bsz * G4];
__device__ __align__(16) float g_logits[Bsz * Av];
// tf32 split activations A = [ipt | h] : [4096][1024]
__device__ __align__(16) float g_Ahi[Bsz * 1024];
__device__ __align__(16) float g_Alo[Bsz * 1024];
// tf32 split weights B = [Wih | Whh] : [2048][1024]
__device__ __align__(16) float g_Bhi[G4 * 1024];
__device__ __align__(16) float g_Blo[G4 * 1024];
__device__ __align__(16) float g_bias[G4];
__device__ int   g_action[Tlen * Bsz];
__device__ float g_lp[Tlen * Bsz];
__device__ float g_ent[Tlen * Bsz];
__device__ unsigned char g_stopped[Bsz];

// ---------------- tf32 split helpers ----------------
__device__ __forceinline__ void tf32split(float a, float &hi, float &lo) {
    float h, l;
    asm("cvt.rna.tf32.f32 %0, %1;" : "=f"(h) : "f"(a));
    float r = a - h;
    asm("cvt.rna.tf32.f32 %0, %1;" : "=f"(l) : "f"(r));
    hi = h; lo = l;
}

__device__ __forceinline__ void mma_tf32(float* d, const uint32_t* a,
                                         uint32_t b0, uint32_t b1) {
    asm volatile(
        "mma.sync.aligned.m16n8k8.row.col.f32.tf32.tf32.f32 "
        "{%0,%1,%2,%3}, {%4,%5,%6,%7}, {%8,%9}, {%0,%1,%2,%3};"
        : "+f"(d[0]), "+f"(d[1]), "+f"(d[2]), "+f"(d[3])
        : "r"(a[0]), "r"(a[1]), "r"(a[2]), "r"(a[3]), "r"(b0), "r"(b1));
}

// ---------------- threefry2x32 (JAX-compatible, 20 rounds) ----------------
__host__ __device__ inline void tf2x32(uint32_t k0, uint32_t k1,
                                       uint32_t x0, uint32_t x1,
                                       uint32_t &o0, uint32_t &o1) {
    uint32_t ks2 = k0 ^ k1 ^ 0x1BD11BDAu;
    x0 += k0; x1 += k1;
#define RL(v, r) (((v) << (r)) | ((v) >> (32 - (r))))
#define R4(a,b,c,d) \
    x0 += x1; x1 = RL(x1, a); x1 ^= x0; \
    x0 += x1; x1 = RL(x1, b); x1 ^= x0; \
    x0 += x1; x1 = RL(x1, c); x1 ^= x0; \
    x0 += x1; x1 = RL(x1, d); x1 ^= x0;
    R4(13, 15, 26, 6)  x0 += k1;  x1 += ks2 + 1u;
    R4(17, 29, 16, 24) x0 += ks2; x1 += k0 + 2u;
    R4(13, 15, 26, 6)  x0 += k0;  x1 += k1 + 3u;
    R4(17, 29, 16, 24) x0 += k1;  x1 += ks2 + 4u;
    R4(13, 15, 26, 6)  x0 += ks2; x1 += k0 + 5u;
#undef R4
#undef RL
    o0 = x0; o1 = x1;
}

__device__ inline float gumbel_from(uint32_t k0, uint32_t k1, uint32_t j) {
    uint32_t o0, o1;
    tf2x32(k0, k1, 0u, j, o0, o1);
    uint32_t bits = o0 ^ o1;
    float u = __uint_as_float((bits >> 9) | 0x3f800000u) - 1.0f;
    const float TINY = 1.1754943508222875e-38f;
    u = u * (1.0f - TINY) + TINY;
    u = fmaxf(TINY, u);
    return -logf(-logf(u));
}

// ---------------- weight split (once per launch) ----------------
__global__ void k_wsplit(const float* __restrict__ Wih,
                         const float* __restrict__ Whh,
                         const float* __restrict__ bih,
                         const float* __restrict__ bhh) {
    int idx = blockIdx.x * blockDim.x + threadIdx.x;
    if (idx < G4 * Hd) {
        int n = idx >> 9, k = idx & 511;
        float hi, lo;
        tf32split(Wih[idx], hi, lo);
        g_Bhi[(size_t)n * 1024 + k] = hi;
        g_Blo[(size_t)n * 1024 + k] = lo;
        tf32split(Whh[idx], hi, lo);
        g_Bhi[(size_t)n * 1024 + 512 + k] = hi;
        g_Blo[(size_t)n * 1024 + 512 + k] = lo;
    }
    if (idx < G4) g_bias[idx] = bih[idx] + bhh[idx];
}

// ---------------- init ----------------
__global__ void k_init(const float* __restrict__ encoded,
                       const float* __restrict__ emb) {
    int idx = blockIdx.x * blockDim.x + threadIdx.x;
    if (idx < Bsz * Hd) {
        int m = idx >> 9, j = idx & 511;
        float e = encoded[idx];
        g_h[idx] = e;
        g_c[idx] = e;
        float hi, lo;
        tf32split(e, hi, lo);
        g_Ahi[(size_t)m * 1024 + 512 + j] = hi;
        g_Alo[(size_t)m * 1024 + 512 + j] = lo;
        float ip = emb[BOSTOK * Hd + j];
        tf32split(ip, hi, lo);
        g_Ahi[(size_t)m * 1024 + j] = hi;
        g_Alo[(size_t)m * 1024 + j] = lo;
    }
    if (idx < Bsz) g_stopped[idx] = 0;
}

// ---------------- gates GEMM (3xTF32 tensor-core): gates = A @ B^T + bias ----------------
// A=[4096][1024] (split), B=[2048][1024] (split). BM=BN=128, BK=16.
// 8 warps (4m x 2n), warp tile 32x64, mma m16n8k8, 3 terms: hh + lh + hl.
__global__ __launch_bounds__(256, 2) void k_gates_tc() {
    __shared__ __align__(16) float As[2][128][20];
    __shared__ __align__(16) float Bs[2][128][20];
    const int t  = threadIdx.x;
    const int bm = blockIdx.y * 128;
    const int bn = blockIdx.x * 128;
    const int w = t >> 5, lane = t & 31;
    const int wm = (w & 3) * 32;    // warp row offset
    const int wn = (w >> 2) * 64;   // warp col offset
    const int lr = lane >> 2;       // 0..7
    const int lc = lane & 3;        // 0..3

    float acc[2][8][4];
#pragma unroll
    for (int a = 0; a < 2; a++)
#pragma unroll
        for (int b = 0; b < 8; b++)
#pragma unroll
            for (int cc = 0; cc < 4; cc++) acc[a][b][cc] = 0.f;

    const int ldr = t >> 1;         // 0..127
    const int ldc = (t & 1) * 8;    // 0 or 8
    const float* pAh = g_Ahi + (size_t)(bm + ldr) * 1024 + ldc;
    const float* pAl = g_Alo + (size_t)(bm + ldr) * 1024 + ldc;
    const float* pBh = g_Bhi + (size_t)(bn + ldr) * 1024 + ldc;
    const float* pBl = g_Blo + (size_t)(bn + ldr) * 1024 + ldc;

    for (int kt = 0; kt < 64; kt++) {
        const int off = kt * 16;
        float4 ah0 = *(const float4*)(pAh + off);
        float4 ah1 = *(const float4*)(pAh + off + 4);
        float4 al0 = *(const float4*)(pAl + off);
        float4 al1 = *(const float4*)(pAl + off + 4);
        float4 bh0 = *(const float4*)(pBh + off);
        float4 bh1 = *(const float4*)(pBh + off + 4);
        float4 bl0 = *(const float4*)(pBl + off);
        float4 bl1 = *(const float4*)(pBl + off + 4);
        __syncthreads();
        *(float4*)&As[0][ldr][ldc]     = ah0;
        *(float4*)&As[0][ldr][ldc + 4] = ah1;
        *(float4*)&As[1][ldr][ldc]     = al0;
        *(float4*)&As[1][ldr][ldc + 4] = al1;
        *(float4*)&Bs[0][ldr][ldc]     = bh0;
        *(float4*)&Bs[0][ldr][ldc + 4] = bh1;
        *(float4*)&Bs[1][ldr][ldc]     = bl0;
        *(float4*)&Bs[1][ldr][ldc + 4] = bl1;
        __syncthreads();
#pragma unroll
        for (int k8 = 0; k8 < 2; k8++) {
            const int kb = k8 * 8 + lc;
            uint32_t af[2][2][4];
#pragma unroll
            for (int mt = 0; mt < 2; mt++) {
                const int row = wm + mt * 16 + lr;
#pragma unroll
                for (int s = 0; s < 2; s++) {
                    af[mt][s][0] = __float_as_uint(As[s][row][kb]);
                    af[mt][s][1] = __float_as_uint(As[s][row + 8][kb]);
                    af[mt][s][2] = __float_as_uint(As[s][row][kb + 4]);
                    af[mt][s][3] = __float_as_uint(As[s][row + 8][kb + 4]);
                }
            }
#pragma unroll
            for (int nt = 0; nt < 8; nt++) {
                const int n = wn + nt * 8 + lr;
                uint32_t vbh0 = __float_as_uint(Bs[0][n][kb]);
                uint32_t vbh1 = __float_as_uint(Bs[0][n][kb + 4]);
                uint32_t vbl0 = __float_as_uint(Bs[1][n][kb]);
                uint32_t vbl1 = __float_as_uint(Bs[1][n][kb + 4]);
#pragma unroll
                for (int mt = 0; mt < 2; mt++) {
                    mma_tf32(acc[mt][nt], af[mt][0], vbh0, vbh1);  // hi*hi
                    mma_tf32(acc[mt][nt], af[mt][1], vbh0, vbh1);  // lo*hi
                    mma_tf32(acc[mt][nt], af[mt][0], vbl0, vbl1);  // hi*lo
                }
            }
        }
    }
    // epilogue: bias + store
#pragma unroll
    for (int mt = 0; mt < 2; mt++) {
        const int r = bm + wm + mt * 16 + lr;
#pragma unroll
        for (int nt = 0; nt < 8; nt++) {
            const int c = bn + wn + nt * 8 + lc * 2;
            const float b0 = g_bias[c], b1 = g_bias[c + 1];
            g_gates[(size_t)r * G4 + c]           = acc[mt][nt][0] + b0;
            g_gates[(size_t)r * G4 + c + 1]       = acc[mt][nt][1] + b1;
            g_gates[(size_t)(r + 8) * G4 + c]     = acc[mt][nt][2] + b0;
            g_gates[(size_t)(r + 8) * G4 + c + 1] = acc[mt][nt][3] + b1;
        }
    }
}

// ---------------- LSTM pointwise (+ tf32 split of h) ----------------
__global__ void k_lstm() {
    int idx = blockIdx.x * blockDim.x + threadIdx.x;
    int m = idx >> 9, jj = idx & 511;
    const float* gr = g_gates + (size_t)m * G4 + jj;
    float gi = gr[0], gf = gr[512], gg = gr[1024], go = gr[1536];
    float si = 1.f / (1.f + expf(-gi));
    float sf = 1.f / (1.f + expf(-gf));
    float so = 1.f / (1.f + expf(-go));
    float c = sf * g_c[idx] + si * tanhf(gg);
    g_c[idx] = c;
    float h = so * tanhf(c);
    g_h[idx] = h;
    float hi, lo;
    tf32split(h, hi, lo);
    g_Ahi[(size_t)m * 1024 + 512 + jj] = hi;
    g_Alo[(size_t)m * 1024 + 512 + jj] = lo;
}

// ---------------- logits GEMM: logits = h @ Wp^T + bp ----------------
__global__ __launch_bounds__(256) void k_logits(const float* __restrict__ Wp,
                                                const float* __restrict__ bp) {
    __shared__ float As[32][64];
    __shared__ float Bs[64][65];
    const int r0 = blockIdx.x * 32;
    const int t = threadIdx.x;
    const int col = t & 63;
    const int rb = (t >> 6) * 8;
    float acc[8] = {0, 0, 0, 0, 0, 0, 0, 0};

    for (int k0 = 0; k0 < 512; k0 += 64) {
        int arow = t >> 3, akk = (t & 7) * 8;
        float4 a0 = *(const float4*)(g_h + (size_t)(r0 + arow) * 512 + k0 + akk);
        float4 a1 = *(const float4*)(g_h + (size_t)(r0 + arow) * 512 + k0 + akk + 4);
        int brow = t >> 2, bkk = (t & 3) * 16;
        float4 w0 = *(const float4*)(Wp + (size_t)brow * 512 + k0 + bkk);
        float4 w1 = *(const float4*)(Wp + (size_t)brow * 512 + k0 + bkk + 4);
        float4 w2 = *(const float4*)(Wp + (size_t)brow * 512 + k0 + bkk + 8);
        float4 w3 = *(const float4*)(Wp + (size_t)brow * 512 + k0 + bkk + 12);
        __syncthreads();
        *(float4*)&As[arow][akk] = a0;
        *(float4*)&As[arow][akk + 4] = a1;
        Bs[brow][bkk + 0] = w0.x;  Bs[brow][bkk + 1] = w0.y;
        Bs[brow][bkk + 2] = w0.z;  Bs[brow][bkk + 3] = w0.w;
        Bs[brow][bkk + 4] = w1.x;  Bs[brow][bkk + 5] = w1.y;
        Bs[brow][bkk + 6] = w1.z;  Bs[brow][bkk + 7] = w1.w;
        Bs[brow][bkk + 8] = w2.x;  Bs[brow][bkk + 9] = w2.y;
        Bs[brow][bkk + 10] = w2.z; Bs[brow][bkk + 11] = w2.w;
        Bs[brow][bkk + 12] = w3.x; Bs[brow][bkk + 13] = w3.y;
        Bs[brow][bkk + 14] = w3.z; Bs[brow][bkk + 15] = w3.w;
        __syncthreads();
#pragma unroll
        for (int k4 = 0; k4 < 16; k4++) {
            float b0 = Bs[col][k4 * 4 + 0];
            float b1 = Bs[col][k4 * 4 + 1];
            float b2 = Bs[col][k4 * 4 + 2];
            float b3 = Bs[col][k4 * 4 + 3];
#pragma unroll
            for (int r = 0; r < 8; r++) {
                float4 a = *(const float4*)&As[rb + r][k4 * 4];
                acc[r] = fmaf(a.x, b0, fmaf(a.y, b1, fmaf(a.z, b2, fmaf(a.w, b3, acc[r]))));
            }
        }
    }
#pragma unroll
    for (int r = 0; r < 8; r++)
        g_logits[(size_t)(r0 + rb + r) * 64 + col] = acc[r] + bp[col];
}

// ---------------- sampling: log_softmax + gumbel argmax + state update ----------------
__global__ void k_sample(const float* __restrict__ emb, int step,
                         uint32_t key0, uint32_t key1) {
    const int b = blockIdx.x;
    const int lane = threadIdx.x;  // 32 threads/block
    float l0 = g_logits[(size_t)b * 64 + lane];
    float l1 = g_logits[(size_t)b * 64 + 32 + lane];

    float m = fmaxf(l0, l1);
#pragma unroll
    for (int off = 16; off > 0; off >>= 1)
        m = fmaxf(m, __shfl_xor_sync(0xffffffffu, m, off));
    float sh0 = l0 - m, sh1 = l1 - m;
    float s = expf(sh0) + expf(sh1);
#pragma unroll
    for (int off = 16; off > 0; off >>= 1)
        s += __shfl_xor_sync(0xffffffffu, s, off);
    float ls = logf(s);
    float lp0 = sh0 - ls, lp1 = sh1 - ls;
    float ent = expf(lp0) * (-lp0) + expf(lp1) * (-lp1);
#pragma unroll
    for (int off = 16; off > 0; off >>= 1)
        ent += __shfl_xor_sync(0xffffffffu, ent, off);

    float z0 = l0 + gumbel_from(key0, key1, (uint32_t)(b * 64 + lane));
    float z1 = l1 + gumbel_from(key0, key1, (uint32_t)(b * 64 + 32 + lane));
    float zb; int ib;
    if (z1 > z0) { zb = z1; ib = lane + 32; } else { zb = z0; ib = lane; }
#pragma unroll
    for (int off = 16; off > 0; off >>= 1) {
        float oz = __shfl_xor_sync(0xffffffffu, zb, off);
        int   oi = __shfl_xor_sync(0xffffffffu, ib, off);
        if (oz > zb || (oz == zb && oi < ib)) { zb = oz; ib = oi; }
    }

    float cand = (ib < 32) ? lp0 : lp1;
    float lp_sel = __shfl_sync(0xffffffffu, cand, ib & 31);
    unsigned char st = g_stopped[b];
    __syncwarp();
    int act = st ? PADTOK : ib;
    if (lane == 0) {
        float live = st ? 0.f : 1.f;
        g_action[step * Bsz + b] = act;
        g_lp[step * Bsz + b] = lp_sel * live;
        g_ent[step * Bsz + b] = ent * live;
        if (!st && ib == 0) g_stopped[b] = 1;
    }
    // write tf32 split of next input embedding into A cols [0,512)
    const float* er = emb + (size_t)act * Hd;
    for (int kk = lane; kk < Hd; kk += 32) {
        float e = er[kk];
        float hi, lo;
        tf32split(e, hi, lo);
        g_Ahi[(size_t)b * 1024 + kk] = hi;
        g_Alo[(size_t)b * 1024 + kk] = lo;
    }
}

// ---------------- final pack: msg | msg_len | lp | ent_avg (float32) ----------------
__global__ void k_pack(float* __restrict__ out) {
    int b = blockIdx.x * blockDim.x + threadIdx.x;
    if (b >= Bsz) return;
    int len = 0;
    float esum = 0.f;
#pragma unroll
    for (int t = 0; t < Tlen; t++) {
        int a = g_action[t * Bsz + b];
        out[(size_t)b * Tlen + t] = (float)a;
        if (a != PADTOK) len++;
        out[(size_t)Bsz * Tlen + Bsz + (size_t)b * Tlen + t] = g_lp[t * Bsz + b];
        esum += g_ent[t * Bsz + b];
    }
    out[(size_t)Bsz * Tlen + b] = (float)len;
    out[2 * (size_t)Bsz * Tlen + Bsz + b] = esum / (float)len;
}

extern "C" void kernel_launch(void* const* d_in, const int* in_sizes, int n_in,
                              void* d_out, int out_size) {
    const float* encoded = (const float*)d_in[0];
    const float* emb     = (const float*)d_in[1];
    const float* Wih     = (const float*)d_in[2];
    const float* Whh     = (const float*)d_in[3];
    const float* bih     = (const float*)d_in[4];
    const float* bhh     = (const float*)d_in[5];
    const float* Wp      = (const float*)d_in[6];
    const float* bp      = (const float*)d_in[7];
    float* out = (float*)d_out;

    // JAX fold-like split (partitionable threefry): key_t = threefry(key(42), (0, t))
    uint32_t k0s[Tlen], k1s[Tlen];
    for (int t = 0; t < Tlen; t++)
        tf2x32(0u, 42u, 0u, (uint32_t)t, k0s[t], k1s[t]);

    k_wsplit<<<(G4 * Hd + 255) / 256, 256>>>(Wih, Whh, bih, bhh);
    k_init<<<(Bsz * Hd + 255) / 256, 256>>>(encoded, emb);
    for (int t = 0; t < Tlen; t++) {
        k_gates_tc<<<dim3(G4 / 128, Bsz / 128), 256>>>();
        k_lstm<<<(Bsz * Hd) / 256, 256>>>();
        k_logits<<<Bsz / 32, 256>>>(Wp, bp);
        k_sample<<<Bsz, 32>>>(emb, t, k0s[t], k1s[t]);
    }
    k_pack<<<(Bsz + 255) / 256, 256>>>(out);
}